// round 15
// baseline (speedup 1.0000x reference)
#include <cuda_runtime.h>
#include <cuda_fp16.h>
#include <cstdint>

#define NLAB 16
#define DIM  256
#define HID  128
#define BATCH 32
#define SEQ  2048
#define G3   384
#define NPAIR 32
#define BC   8
#define GIP  392
#define TS   8              // timesteps per produced segment (M = TS*BC = 64)

// smem byte offsets (fused kernel)
#define OFF_H    0          // h_sm[2][8][136] half            = 4352
#define OFF_MASK 4352       // mask[8][64] u32                 = 2048
#define OFF_LEN  6400       // len[8] int                      = 32
#define OFF_MB   6432       // mbar: full0,full1,empty0,empty1 = 32
#define OFF_GI   6464       // gi ring [2][64][392] half       = 100352
#define OFF_A    106816     // A tile [4 kc][64][64] half      = 32768
#define OFF_B    139584     // B ring: pass1 3x[256][32]h=49152 / pass2 3x[128][32]h
#define SMEM_TOTAL 188736

__device__ __half g_xh[(size_t)BATCH * SEQ * DIM];
__device__ __half g_wh[(size_t)NPAIR * G3 * DIM];

__device__ __forceinline__ void mma_f16(float* c, const uint32_t* a, const uint32_t* b) {
    asm volatile(
        "mma.sync.aligned.m16n8k16.row.col.f32.f16.f16.f32 "
        "{%0,%1,%2,%3}, {%4,%5,%6,%7}, {%8,%9}, {%0,%1,%2,%3};\n"
        : "+f"(c[0]), "+f"(c[1]), "+f"(c[2]), "+f"(c[3])
        : "r"(a[0]), "r"(a[1]), "r"(a[2]), "r"(a[3]), "r"(b[0]), "r"(b[1]));
}
__device__ __forceinline__ void mma_f16h(uint32_t* c, const uint32_t* a, const uint32_t* b) {
    asm volatile(
        "mma.sync.aligned.m16n8k16.row.col.f16.f16.f16.f16 "
        "{%0,%1}, {%2,%3,%4,%5}, {%6,%7}, {%0,%1};\n"
        : "+r"(c[0]), "+r"(c[1])
        : "r"(a[0]), "r"(a[1]), "r"(a[2]), "r"(a[3]), "r"(b[0]), "r"(b[1]));
}
__device__ __forceinline__ void ldm_x4(uint32_t& r0, uint32_t& r1, uint32_t& r2, uint32_t& r3,
                                       uint32_t addr) {
    asm volatile("ldmatrix.sync.aligned.m8n8.x4.shared.b16 {%0,%1,%2,%3}, [%4];"
                 : "=r"(r0), "=r"(r1), "=r"(r2), "=r"(r3) : "r"(addr));
}
__device__ __forceinline__ uint32_t f2h2(float a, float b) {
    __half2 h = __floats2half2_rn(a, b);
    return *(uint32_t*)&h;
}
__device__ __forceinline__ float tanh_mufu(float x) {
    float y;
    asm("tanh.approx.f32 %0, %1;" : "=f"(y) : "f"(x));
    return y;
}
__device__ __forceinline__ float sigmoid_fast(float x) {
    return fmaf(tanh_mufu(0.5f * x), 0.5f, 0.5f);
}
__device__ __forceinline__ void mbar_init(uint32_t mbar, uint32_t cnt) {
    asm volatile("mbarrier.init.shared.b64 [%0], %1;" :: "r"(mbar), "r"(cnt) : "memory");
}
__device__ __forceinline__ void mbar_arrive(uint32_t mbar) {
    asm volatile("mbarrier.arrive.release.cta.shared::cta.b64 _, [%0];"
                 :: "r"(mbar) : "memory");
}
__device__ __forceinline__ void mbar_wait(uint32_t mbar, uint32_t parity) {
    asm volatile(
        "{\n\t.reg .pred P1;\n\t"
        "WAIT_%=:\n\t"
        "mbarrier.try_wait.parity.acquire.cta.shared::cta.b64 P1, [%0], %1, 0x989680;\n\t"
        "@P1 bra.uni DONE_%=;\n\t"
        "bra.uni WAIT_%=;\n\t"
        "DONE_%=:\n\t}"
        :: "r"(mbar), "r"(parity) : "memory");
}

// ===========================================================================
// Phase 0: convert x and Wih to fp16 once.
// ===========================================================================
__global__ __launch_bounds__(256) void convert_kernel(
    const float* __restrict__ x, const float* __restrict__ Wih)
{
    const size_t nx = (size_t)BATCH * SEQ * DIM / 4;
    const size_t nw = (size_t)NPAIR * G3 * DIM / 4;
    size_t i = (size_t)blockIdx.x * blockDim.x + threadIdx.x;
    if (i < nx) {
        float4 v = ((const float4*)x)[i];
        __half2* d = (__half2*)g_xh;
        d[2 * i]     = __floats2half2_rn(v.x, v.y);
        d[2 * i + 1] = __floats2half2_rn(v.z, v.w);
    } else if (i < nx + nw) {
        size_t j = i - nx;
        float4 v = ((const float4*)Wih)[j];
        __half2* d = (__half2*)g_wh;
        d[2 * j]     = __floats2half2_rn(v.x, v.y);
        d[2 * j + 1] = __floats2half2_rn(v.z, v.w);
    }
}

// ===========================================================================
// Fused kernel. Block = (chunk, pair), 384 threads.
//  warps 0-7 : recurrence (hoisted loads; biases in gate math)
//  warps 8-11: producer — gi GEMM per 8-step segment, TWO passes over N
//              (pass1 r/z rows 0-255 f16 accum; pass2 n rows 256-383 f32)
//              to halve peak accumulator registers (no spills).
// Sync: mbarriers full[2] (128 arrivals) / empty[2] (256 arrivals);
//       rec-internal bar.sync 1,256; producer-internal bar.sync 2,128.
// ===========================================================================
__global__ __launch_bounds__(384, 1) void gru_fused_kernel(
    const float* __restrict__ Whh, const float* __restrict__ bih,
    const float* __restrict__ bhh, const int* __restrict__ amask,
    float* __restrict__ out)
{
    extern __shared__ char dyn[];
    __half (*h_sm)[BC][136] = (__half(*)[BC][136])(dyn + OFF_H);
    uint32_t (*mask_sm)[64] = (uint32_t(*)[64])(dyn + OFF_MASK);
    int* len_sm             = (int*)(dyn + OFF_LEN);
    __half* gi_sm           = (__half*)(dyn + OFF_GI);
    const uint32_t smem_u   = (uint32_t)__cvta_generic_to_shared(dyn);
    const uint32_t mb_full0 = smem_u + OFF_MB;
    const uint32_t mb_empty0 = smem_u + OFF_MB + 16;

    const int tid = threadIdx.x;
    const int wid = tid >> 5, lane = tid & 31;
    const int gid = lane >> 2, tig = lane & 3;
    const int chunk = blockIdx.x;     // 0..3
    const int p     = blockIdx.y;     // 0..31
    const int l = p >> 1, dir = p & 1;
    const int b0 = chunk * BC;

    // ---- shared setup ----
    if (tid == 0) {
        mbar_init(mb_full0, 128);
        mbar_init(mb_full0 + 8, 128);
        mbar_init(mb_empty0, 256);
        mbar_init(mb_empty0 + 8, 256);
    }
    if (wid < 8) {
        const int* mb = amask + (size_t)(b0 + wid) * SEQ;
        int cnt = 0;
        for (int w = 0; w < 64; w++) {
            unsigned bit = (mb[w * 32 + lane] != 0) ? 1u : 0u;
            unsigned word = __ballot_sync(0xffffffffu, bit);
            if (lane == 0) mask_sm[wid][w] = word;
            cnt += __popc(word);
        }
        if (lane == 0) len_sm[wid] = cnt;
    }
    for (int i = tid; i < 2 * BC * 136; i += 384) (&h_sm[0][0][0])[i] = __float2half(0.0f);
    __syncthreads();

    int maxlen = len_sm[0];
#pragma unroll
    for (int b = 1; b < BC; b++) maxlen = max(maxlen, len_sm[b]);
    const int nseg = (maxlen + TS - 1) / TS;

    if (wid < 8) {
        // =================== CONSUMER: recurrence ===================
        const float* Whh_p = Whh + (size_t)p * G3 * HID;
        const float* bih_p = bih + (size_t)p * G3;
        const float* bhh_p = bhh + (size_t)p * G3;

        uint32_t A[3][8][4];
#pragma unroll
        for (int i = 0; i < 3; i++) {
            int r0 = i * 128 + 16 * wid + gid;
            int r1 = r0 + 8;
#pragma unroll
            for (int kk = 0; kk < 8; kk++) {
                int k0 = kk * 16 + tig * 2;
                int k1 = k0 + 8;
                float2 v00 = *(const float2*)(Whh_p + (size_t)r0 * HID + k0);
                float2 v10 = *(const float2*)(Whh_p + (size_t)r1 * HID + k0);
                float2 v01 = *(const float2*)(Whh_p + (size_t)r0 * HID + k1);
                float2 v11 = *(const float2*)(Whh_p + (size_t)r1 * HID + k1);
                A[i][kk][0] = f2h2(v00.x, v00.y);
                A[i][kk][1] = f2h2(v10.x, v10.y);
                A[i][kk][2] = f2h2(v01.x, v01.y);
                A[i][kk][3] = f2h2(v11.x, v11.y);
            }
        }
        const int j0 = 16 * wid + gid;
        float br[2], bz[2], bin[2], bnh[2];
#pragma unroll
        for (int m = 0; m < 2; m++) {
            int j = j0 + 8 * m;
            br[m]  = bih_p[j]       + bhh_p[j];
            bz[m]  = bih_p[128 + j] + bhh_p[128 + j];
            bin[m] = bih_p[256 + j];
            bnh[m] = bhh_p[256 + j];
        }

        const int bq0 = 2 * tig, bq1 = 2 * tig + 1;
        float h[4] = {0.f, 0.f, 0.f, 0.f};

        for (int s = 0; s < maxlen; s++) {
            const int t = dir ? (maxlen - 1 - s) : s;
            const int tt = s & (TS - 1);
            const int buf = (s >> 3) & 1;
            const int cur = s & 1, nxt = cur ^ 1;

            if (tt == 0) mbar_wait(mb_full0 + 8 * buf, (s >> 4) & 1);

            // ---- hoisted loads: h B-fragments, gi, masks (off critical path) ----
            uint32_t bfr[8][2];
#pragma unroll
            for (int kk = 0; kk < 8; kk++) {
                bfr[kk][0] = *(const uint32_t*)&h_sm[cur][gid][kk * 16 + tig * 2];
                bfr[kk][1] = *(const uint32_t*)&h_sm[cur][gid][kk * 16 + tig * 2 + 8];
            }
            const __half* gp0 = gi_sm + (size_t)(buf * 64 + tt * 8 + bq0) * GIP;
            const __half* gp1 = gp0 + GIP;
            float gir[4], giz[4], gin[4];
#pragma unroll
            for (int m = 0; m < 2; m++) {
                int j = j0 + 8 * m;
                gir[2 * m]     = __half2float(gp0[j]);
                gir[2 * m + 1] = __half2float(gp1[j]);
                giz[2 * m]     = __half2float(gp0[128 + j]);
                giz[2 * m + 1] = __half2float(gp1[128 + j]);
                gin[2 * m]     = __half2float(gp0[256 + j]);
                gin[2 * m + 1] = __half2float(gp1[256 + j]);
            }
            const bool v0 = (mask_sm[bq0][t >> 5] >> (t & 31)) & 1u;
            const bool v1 = (mask_sm[bq1][t >> 5] >> (t & 31)) & 1u;

            // ---- MMA chains ----
            float cr[4] = {0.f, 0.f, 0.f, 0.f};
            float cz[4] = {0.f, 0.f, 0.f, 0.f};
            float cn[4];
            cn[0] = bnh[0]; cn[1] = bnh[0]; cn[2] = bnh[1]; cn[3] = bnh[1];
#pragma unroll
            for (int kk = 0; kk < 8; kk++) {
                mma_f16(cr, A[0][kk], bfr[kk]);
                mma_f16(cz, A[1][kk], bfr[kk]);
                mma_f16(cn, A[2][kk], bfr[kk]);
            }

            // ---- gates ----
#pragma unroll
            for (int m = 0; m < 2; m++) {
                const int j = j0 + 8 * m;
#pragma unroll
                for (int bs = 0; bs < 2; bs++) {
                    const int q = 2 * m + bs;
                    float r = sigmoid_fast(gir[q] + cr[q] + br[m]);
                    float z = sigmoid_fast(giz[q] + cz[q] + bz[m]);
                    float n = tanh_mufu(gin[q] + bin[m] + r * cn[q]);
                    float hn = n + z * (h[q] - n);
                    bool valid = bs ? v1 : v0;
                    if (valid) h[q] = hn;
                    h_sm[nxt][bs ? bq1 : bq0][j] = __float2half(h[q]);
                }
            }
            asm volatile("bar.sync 1, 256;" ::: "memory");
            if (tt == TS - 1 || s == maxlen - 1)
                mbar_arrive(mb_empty0 + 8 * buf);
        }

#pragma unroll
        for (int m = 0; m < 2; m++) {
            const int j = j0 + 8 * m;
            const int col = (dir == 1) ? j : (128 + j);
#pragma unroll
            for (int bs = 0; bs < 2; bs++) {
                const int q = 2 * m + bs;
                const int bg = b0 + (bs ? bq1 : bq0);
                out[((size_t)bg * NLAB + l) * 256 + col] = h[q];
            }
        }
    } else {
        // =================== PRODUCER: gi GEMM, 2 passes ===================
        const int pw = wid - 8;            // 0..3
        const int ptid = tid - 256;        // 0..127
        const __half* Wp = g_wh + (size_t)p * G3 * DIM;
        const uint32_t Asm = smem_u + OFF_A;
        const uint32_t Bsm = smem_u + OFF_B;
        const int lrow = lane & 15;
        const int lhi  = lane >> 4;
        const int rB_lo = ((lane >> 4) << 3) + (lane & 7);
        const int cB = (lane >> 3) & 1;

        // B chunk loaders: rows [rbase, rbase+nrows) of Wp, k-chunk kc (32 wide),
        // into ring slot st with given row-count stride.
        auto issueB = [&](int rbase, int nrows, int kc, int st) {
            const int iters = nrows * 4 / 128;       // chunks of 16B per thread
            for (int i = 0; i < iters; i++) {
                int flat = ptid + 128 * i;
                int row = flat >> 2, c = flat & 3;
                const __half* src = Wp + (size_t)(rbase + row) * DIM + kc * 32 + c * 8;
                uint32_t dst = Bsm + (uint32_t)(st * nrows * 64 + row * 64 +
                                                ((c ^ (row & 3)) * 16));
                asm volatile("cp.async.cg.shared.global [%0], [%1], 16;\n"
                             :: "r"(dst), "l"(src) : "memory");
            }
        };

        for (int j = 0; j < nseg; j++) {
            const int buf = j & 1;
            if (j >= 2) mbar_wait(mb_empty0 + 8 * buf, ((j - 2) >> 1) & 1);
            asm volatile("bar.sync 2, 128;" ::: "memory");   // prev segment reads done

            // A tile (M=64 rows, K=256)
            const int tbase = dir ? (maxlen - 1 - TS * j) : TS * j;
#pragma unroll
            for (int i = 0; i < 16; i++) {
                int flat = ptid + 128 * i;
                int kc = flat >> 9, rem = flat & 511;
                int row = rem >> 3, c = rem & 7;
                int b = row & 7, tt = row >> 3;
                int t = dir ? (tbase - tt) : (tbase + tt);
                t = min(max(t, 0), SEQ - 1);
                const __half* src = g_xh + ((size_t)(b0 + b) * SEQ + t) * DIM + kc * 64 + c * 8;
                uint32_t dst = Asm + (uint32_t)(kc * 8192 + row * 128 + ((c ^ (row & 7)) * 16));
                asm volatile("cp.async.cg.shared.global [%0], [%1], 16;\n"
                             :: "r"(dst), "l"(src) : "memory");
            }
            issueB(0, 256, 0, 0);
            asm volatile("cp.async.commit_group;\n" ::: "memory");  // group: A + b0
            issueB(0, 256, 1, 1);
            asm volatile("cp.async.commit_group;\n" ::: "memory");  // group: b1

            // ---- PASS 1: r/z rows 0-255, f16 accumulators ----
            uint32_t accH[4][8][2];
#pragma unroll
            for (int mt = 0; mt < 4; mt++)
#pragma unroll
                for (int e = 0; e < 8; e++) { accH[mt][e][0] = 0u; accH[mt][e][1] = 0u; }

            for (int kc = 0; kc < 8; kc++) {
                asm volatile("cp.async.wait_group 1;\n" ::: "memory");
                asm volatile("bar.sync 2, 128;" ::: "memory");
                if (kc + 2 < 8) issueB(0, 256, kc + 2, (kc + 2) % 3);
                asm volatile("cp.async.commit_group;\n" ::: "memory");
                const uint32_t Bb = Bsm + (uint32_t)((kc % 3) * 16384);
#pragma unroll
                for (int ksb = 0; ksb < 2; ksb++) {
                    const int ks = kc * 2 + ksb;
                    const uint32_t Abk = Asm + (uint32_t)((ks >> 2) * 8192);
                    const int ach = ((ks & 3) * 2 + lhi);
                    uint32_t bfrz[4][4];
#pragma unroll
                    for (int pr = 0; pr < 4; pr++) {
                        int nb = (pr < 2 ? 0 : 128) + 32 * pw + (pr & 1) * 16;
                        uint32_t addr = Bb + (uint32_t)((nb + rB_lo) * 64 +
                                        (((ksb * 2 + cB) ^ ((nb + rB_lo) & 3)) * 16));
                        ldm_x4(bfrz[pr][0], bfrz[pr][1], bfrz[pr][2], bfrz[pr][3], addr);
                    }
#pragma unroll
                    for (int mt = 0; mt < 4; mt++) {
                        int rA = mt * 16 + lrow;
                        uint32_t af[4];
                        uint32_t addr = Abk + (uint32_t)(rA * 128 + ((ach ^ (rA & 7)) * 16));
                        ldm_x4(af[0], af[1], af[2], af[3], addr);
#pragma unroll
                        for (int pr = 0; pr < 4; pr++) {
                            mma_f16h(accH[mt][2 * pr],     af, &bfrz[pr][0]);
                            mma_f16h(accH[mt][2 * pr + 1], af, &bfrz[pr][2]);
                        }
                    }
                }
            }
            // pass-1 epilogue: store rz
            __half* gib = gi_sm + (size_t)buf * 64 * GIP;
#pragma unroll
            for (int mt = 0; mt < 4; mt++) {
                int rr0 = mt * 16 + gid, rr1 = rr0 + 8;
#pragma unroll
                for (int e = 0; e < 8; e++) {
                    int col = ((e < 4) ? (32 * pw + 8 * e) : (128 + 32 * pw + 8 * (e - 4)))
                              + 2 * tig;
                    *(uint32_t*)(gib + (size_t)rr0 * GIP + col) = accH[mt][e][0];
                    *(uint32_t*)(gib + (size_t)rr1 * GIP + col) = accH[mt][e][1];
                }
            }

            // ---- PASS 2: n rows 256-383, f32 accumulators ----
            asm volatile("cp.async.wait_group 0;\n" ::: "memory");
            asm volatile("bar.sync 2, 128;" ::: "memory");     // pass-1 B reads done
            issueB(256, 128, 0, 0);
            asm volatile("cp.async.commit_group;\n" ::: "memory");
            issueB(256, 128, 1, 1);
            asm volatile("cp.async.commit_group;\n" ::: "memory");

            float accF[4][4][4];
#pragma unroll
            for (int mt = 0; mt < 4; mt++)
#pragma unroll
                for (int f = 0; f < 4; f++)
#pragma unroll
                    for (int q = 0; q < 4; q++) accF[mt][f][q] = 0.0f;

            for (int kc = 0; kc < 8; kc++) {
                asm volatile("cp.async.wait_group 1;\n" ::: "memory");
                asm volatile("bar.sync 2, 128;" ::: "memory");
                if (kc + 2 < 8) issueB(256, 128, kc + 2, (kc + 2) % 3);
                asm volatile("cp.async.commit_group;\n" ::: "memory");
                const uint32_t Bb = Bsm + (uint32_t)((kc % 3) * 8192);
#pragma unroll
                for (int ksb = 0; ksb < 2; ksb++) {
                    const int ks = kc * 2 + ksb;
                    const uint32_t Abk = Asm + (uint32_t)((ks >> 2) * 8192);
                    const int ach = ((ks & 3) * 2 + lhi);
                    uint32_t bfn[2][4];
#pragma unroll
                    for (int pr = 0; pr < 2; pr++) {
                        int nb = 32 * pw + pr * 16;          // local rows 0..127
                        uint32_t addr = Bb + (uint32_t)((nb + rB_lo) * 64 +
                                        (((ksb * 2 + cB) ^ ((nb + rB_lo) & 3)) * 16));
                        ldm_x4(bfn[pr][0], bfn[pr][1], bfn[pr][2], bfn[pr][3], addr);
                    }
#pragma unroll
                    for (int mt = 0; mt < 4; mt++) {
                        int rA = mt * 16 + lrow;
                        uint32_t af[4];
                        uint32_t addr = Abk + (uint32_t)(rA * 128 + ((ach ^ (rA & 7)) * 16));
                        ldm_x4(af[0], af[1], af[2], af[3], addr);
                        mma_f16(accF[mt][0], af, &bfn[0][0]);
                        mma_f16(accF[mt][1], af, &bfn[0][2]);
                        mma_f16(accF[mt][2], af, &bfn[1][0]);
                        mma_f16(accF[mt][3], af, &bfn[1][2]);
                    }
                }
            }
            // pass-2 epilogue: store n
#pragma unroll
            for (int mt = 0; mt < 4; mt++) {
                int rr0 = mt * 16 + gid, rr1 = rr0 + 8;
#pragma unroll
                for (int f = 0; f < 4; f++) {
                    int col = 256 + 32 * pw + 8 * f + 2 * tig;
                    *(uint32_t*)(gib + (size_t)rr0 * GIP + col) =
                        f2h2(accF[mt][f][0], accF[mt][f][1]);
                    *(uint32_t*)(gib + (size_t)rr1 * GIP + col) =
                        f2h2(accF[mt][f][2], accF[mt][f][3]);
                }
            }
            asm volatile("cp.async.wait_group 0;\n" ::: "memory");
            mbar_arrive(mb_full0 + 8 * buf);
        }
    }
}

extern "C" void kernel_launch(void* const* d_in, const int* in_sizes, int n_in,
                              void* d_out, int out_size) {
    const float* x     = (const float*)d_in[0];
    const int*   amask = (const int*)d_in[1];
    // d_in[2] = label: always arange(L) by construction.
    const float* Wih   = (const float*)d_in[3];
    const float* Whh   = (const float*)d_in[4];
    const float* bih   = (const float*)d_in[5];
    const float* bhh   = (const float*)d_in[6];
    float*       out   = (float*)d_out;

    cudaFuncSetAttribute(gru_fused_kernel, cudaFuncAttributeMaxDynamicSharedMemorySize,
                         SMEM_TOTAL);

    const size_t nchunks = (size_t)BATCH * SEQ * DIM / 4 + (size_t)NPAIR * G3 * DIM / 4;
    convert_kernel<<<(unsigned)((nchunks + 255) / 256), 256>>>(x, Wih);

    dim3 g(4, 32);
    gru_fused_kernel<<<g, 384, SMEM_TOTAL>>>(Whh, bih, bhh, amask, out);
}

// round 17
// speedup vs baseline: 1.8013x; 1.8013x over previous
#include <cuda_runtime.h>
#include <cuda_fp16.h>
#include <cstdint>

#define NLAB 16
#define DIM  256
#define HID  128
#define BATCH 32
#define SEQ  2048
#define G3   384
#define NPAIR 32
#define BC   8
#define GIP  392
#define TS   8              // timesteps per produced segment (M = TS*BC = 64)

// smem byte offsets (fused kernel)
#define OFF_H    0          // h_sm[2][8][136] half            = 4352
#define OFF_MASK 4352       // mask[8][64] u32                 = 2048
#define OFF_LEN  6400       // len[8] int                      = 32
#define OFF_MB   6432       // mbar: full0,full1,empty0,empty1 = 32
#define OFF_GI   6464       // gi ring [2][64][392] half       = 100352
#define OFF_A    106816     // A tile [4 kc][64][64] half      = 32768
#define OFF_B    139584     // B ring [2][384][32] half        = 49152
#define SMEM_TOTAL 188736

__device__ __half g_xh[(size_t)BATCH * SEQ * DIM];
__device__ __half g_wh[(size_t)NPAIR * G3 * DIM];

__device__ __forceinline__ void mma_f16(float* c, const uint32_t* a, const uint32_t* b) {
    asm volatile(
        "mma.sync.aligned.m16n8k16.row.col.f32.f16.f16.f32 "
        "{%0,%1,%2,%3}, {%4,%5,%6,%7}, {%8,%9}, {%0,%1,%2,%3};\n"
        : "+f"(c[0]), "+f"(c[1]), "+f"(c[2]), "+f"(c[3])
        : "r"(a[0]), "r"(a[1]), "r"(a[2]), "r"(a[3]), "r"(b[0]), "r"(b[1]));
}
__device__ __forceinline__ void mma_f16h(uint32_t* c, const uint32_t* a, const uint32_t* b) {
    asm volatile(
        "mma.sync.aligned.m16n8k16.row.col.f16.f16.f16.f16 "
        "{%0,%1}, {%2,%3,%4,%5}, {%6,%7}, {%0,%1};\n"
        : "+r"(c[0]), "+r"(c[1])
        : "r"(a[0]), "r"(a[1]), "r"(a[2]), "r"(a[3]), "r"(b[0]), "r"(b[1]));
}
__device__ __forceinline__ void ldm_x4(uint32_t& r0, uint32_t& r1, uint32_t& r2, uint32_t& r3,
                                       uint32_t addr) {
    asm volatile("ldmatrix.sync.aligned.m8n8.x4.shared.b16 {%0,%1,%2,%3}, [%4];"
                 : "=r"(r0), "=r"(r1), "=r"(r2), "=r"(r3) : "r"(addr));
}
__device__ __forceinline__ uint32_t f2h2(float a, float b) {
    __half2 h = __floats2half2_rn(a, b);
    return *(uint32_t*)&h;
}
__device__ __forceinline__ float tanh_mufu(float x) {
    float y;
    asm("tanh.approx.f32 %0, %1;" : "=f"(y) : "f"(x));
    return y;
}
__device__ __forceinline__ float sigmoid_fast(float x) {
    return fmaf(tanh_mufu(0.5f * x), 0.5f, 0.5f);
}
__device__ __forceinline__ void mbar_init(uint32_t mbar, uint32_t cnt) {
    asm volatile("mbarrier.init.shared.b64 [%0], %1;" :: "r"(mbar), "r"(cnt) : "memory");
}
__device__ __forceinline__ void mbar_arrive(uint32_t mbar) {
    asm volatile("mbarrier.arrive.release.cta.shared::cta.b64 _, [%0];"
                 :: "r"(mbar) : "memory");
}
__device__ __forceinline__ void mbar_wait(uint32_t mbar, uint32_t parity) {
    asm volatile(
        "{\n\t.reg .pred P1;\n\t"
        "WAIT_%=:\n\t"
        "mbarrier.try_wait.parity.acquire.cta.shared::cta.b64 P1, [%0], %1, 0x989680;\n\t"
        "@P1 bra.uni DONE_%=;\n\t"
        "bra.uni WAIT_%=;\n\t"
        "DONE_%=:\n\t}"
        :: "r"(mbar), "r"(parity) : "memory");
}

// ===========================================================================
// Phase 0: convert x and Wih to fp16 once.
// ===========================================================================
__global__ __launch_bounds__(256) void convert_kernel(
    const float* __restrict__ x, const float* __restrict__ Wih)
{
    const size_t nx = (size_t)BATCH * SEQ * DIM / 4;
    const size_t nw = (size_t)NPAIR * G3 * DIM / 4;
    size_t i = (size_t)blockIdx.x * blockDim.x + threadIdx.x;
    if (i < nx) {
        float4 v = ((const float4*)x)[i];
        __half2* d = (__half2*)g_xh;
        d[2 * i]     = __floats2half2_rn(v.x, v.y);
        d[2 * i + 1] = __floats2half2_rn(v.z, v.w);
    } else if (i < nx + nw) {
        size_t j = i - nx;
        float4 v = ((const float4*)Wih)[j];
        __half2* d = (__half2*)g_wh;
        d[2 * j]     = __floats2half2_rn(v.x, v.y);
        d[2 * j + 1] = __floats2half2_rn(v.z, v.w);
    }
}

// ===========================================================================
// Fused kernel. Block = (chunk, pair), 384 threads.
//  warps 0-7 : recurrence (hoisted loads ahead of the MMA chain)
//  warps 8-11: producer — gi GEMM per 8-step segment (single pass, r/z f16 +
//              n f32 accumulators interleaved; the R14 structure).
// Sync: mbarriers full[2] (128 arrivals) / empty[2] (256 arrivals);
//       rec-internal bar.sync 1,256; producer-internal bar.sync 2,128.
// ===========================================================================
__global__ __launch_bounds__(384, 1) void gru_fused_kernel(
    const float* __restrict__ Whh, const float* __restrict__ bih,
    const float* __restrict__ bhh, const int* __restrict__ amask,
    float* __restrict__ out)
{
    extern __shared__ char dyn[];
    __half (*h_sm)[BC][136] = (__half(*)[BC][136])(dyn + OFF_H);
    uint32_t (*mask_sm)[64] = (uint32_t(*)[64])(dyn + OFF_MASK);
    int* len_sm             = (int*)(dyn + OFF_LEN);
    __half* gi_sm           = (__half*)(dyn + OFF_GI);
    const uint32_t smem_u   = (uint32_t)__cvta_generic_to_shared(dyn);
    const uint32_t mb_full0 = smem_u + OFF_MB;
    const uint32_t mb_empty0 = smem_u + OFF_MB + 16;

    const int tid = threadIdx.x;
    const int wid = tid >> 5, lane = tid & 31;
    const int gid = lane >> 2, tig = lane & 3;
    const int chunk = blockIdx.x;     // 0..3
    const int p     = blockIdx.y;     // 0..31
    const int l = p >> 1, dir = p & 1;
    const int b0 = chunk * BC;

    // ---- shared setup (all 384 threads) ----
    if (tid == 0) {
        mbar_init(mb_full0, 128);
        mbar_init(mb_full0 + 8, 128);
        mbar_init(mb_empty0, 256);
        mbar_init(mb_empty0 + 8, 256);
    }
    if (wid < 8) {
        const int* mb = amask + (size_t)(b0 + wid) * SEQ;
        int cnt = 0;
        for (int w = 0; w < 64; w++) {
            unsigned bit = (mb[w * 32 + lane] != 0) ? 1u : 0u;
            unsigned word = __ballot_sync(0xffffffffu, bit);
            if (lane == 0) mask_sm[wid][w] = word;
            cnt += __popc(word);
        }
        if (lane == 0) len_sm[wid] = cnt;
    }
    for (int i = tid; i < 2 * BC * 136; i += 384) (&h_sm[0][0][0])[i] = __float2half(0.0f);
    __syncthreads();

    int maxlen = len_sm[0];
#pragma unroll
    for (int b = 1; b < BC; b++) maxlen = max(maxlen, len_sm[b]);
    const int nseg = (maxlen + TS - 1) / TS;

    if (wid < 8) {
        // =================== CONSUMER: recurrence ===================
        const float* Whh_p = Whh + (size_t)p * G3 * HID;
        const float* bih_p = bih + (size_t)p * G3;
        const float* bhh_p = bhh + (size_t)p * G3;

        uint32_t A[3][8][4];
#pragma unroll
        for (int i = 0; i < 3; i++) {
            int r0 = i * 128 + 16 * wid + gid;
            int r1 = r0 + 8;
#pragma unroll
            for (int kk = 0; kk < 8; kk++) {
                int k0 = kk * 16 + tig * 2;
                int k1 = k0 + 8;
                float2 v00 = *(const float2*)(Whh_p + (size_t)r0 * HID + k0);
                float2 v10 = *(const float2*)(Whh_p + (size_t)r1 * HID + k0);
                float2 v01 = *(const float2*)(Whh_p + (size_t)r0 * HID + k1);
                float2 v11 = *(const float2*)(Whh_p + (size_t)r1 * HID + k1);
                A[i][kk][0] = f2h2(v00.x, v00.y);
                A[i][kk][1] = f2h2(v10.x, v10.y);
                A[i][kk][2] = f2h2(v01.x, v01.y);
                A[i][kk][3] = f2h2(v11.x, v11.y);
            }
        }
        const int j0 = 16 * wid + gid;
        float br[2], bz[2], bin[2], bnh[2];
#pragma unroll
        for (int m = 0; m < 2; m++) {
            int j = j0 + 8 * m;
            br[m]  = bih_p[j]       + bhh_p[j];
            bz[m]  = bih_p[128 + j] + bhh_p[128 + j];
            bin[m] = bih_p[256 + j];
            bnh[m] = bhh_p[256 + j];
        }

        const int bq0 = 2 * tig, bq1 = 2 * tig + 1;
        float h[4] = {0.f, 0.f, 0.f, 0.f};

        for (int s = 0; s < maxlen; s++) {
            const int t = dir ? (maxlen - 1 - s) : s;
            const int tt = s & (TS - 1);
            const int buf = (s >> 3) & 1;
            const int cur = s & 1, nxt = cur ^ 1;

            if (tt == 0) mbar_wait(mb_full0 + 8 * buf, (s >> 4) & 1);

            // ---- hoisted loads: h B-fragments, gi, masks (overlap MMA issue) ----
            uint32_t bfr[8][2];
#pragma unroll
            for (int kk = 0; kk < 8; kk++) {
                bfr[kk][0] = *(const uint32_t*)&h_sm[cur][gid][kk * 16 + tig * 2];
                bfr[kk][1] = *(const uint32_t*)&h_sm[cur][gid][kk * 16 + tig * 2 + 8];
            }
            const __half* gp0 = gi_sm + (size_t)(buf * 64 + tt * 8 + bq0) * GIP;
            const __half* gp1 = gp0 + GIP;
            float gir[4], giz[4], gin[4];
#pragma unroll
            for (int m = 0; m < 2; m++) {
                int j = j0 + 8 * m;
                gir[2 * m]     = __half2float(gp0[j]);
                gir[2 * m + 1] = __half2float(gp1[j]);
                giz[2 * m]     = __half2float(gp0[128 + j]);
                giz[2 * m + 1] = __half2float(gp1[128 + j]);
                gin[2 * m]     = __half2float(gp0[256 + j]);
                gin[2 * m + 1] = __half2float(gp1[256 + j]);
            }
            const bool v0 = (mask_sm[bq0][t >> 5] >> (t & 31)) & 1u;
            const bool v1 = (mask_sm[bq1][t >> 5] >> (t & 31)) & 1u;

            // ---- MMA chains ----
            float cr[4] = {0.f, 0.f, 0.f, 0.f};
            float cz[4] = {0.f, 0.f, 0.f, 0.f};
            float cn[4];
            cn[0] = bnh[0]; cn[1] = bnh[0]; cn[2] = bnh[1]; cn[3] = bnh[1];
#pragma unroll
            for (int kk = 0; kk < 8; kk++) {
                mma_f16(cr, A[0][kk], bfr[kk]);
                mma_f16(cz, A[1][kk], bfr[kk]);
                mma_f16(cn, A[2][kk], bfr[kk]);
            }

            // ---- gates ----
#pragma unroll
            for (int m = 0; m < 2; m++) {
                const int j = j0 + 8 * m;
#pragma unroll
                for (int bs = 0; bs < 2; bs++) {
                    const int q = 2 * m + bs;
                    float r = sigmoid_fast(gir[q] + cr[q] + br[m]);
                    float z = sigmoid_fast(giz[q] + cz[q] + bz[m]);
                    float n = tanh_mufu(gin[q] + bin[m] + r * cn[q]);
                    float hn = n + z * (h[q] - n);
                    bool valid = bs ? v1 : v0;
                    if (valid) h[q] = hn;
                    h_sm[nxt][bs ? bq1 : bq0][j] = __float2half(h[q]);
                }
            }
            asm volatile("bar.sync 1, 256;" ::: "memory");   // rec warps only
            if (tt == TS - 1 || s == maxlen - 1)
                mbar_arrive(mb_empty0 + 8 * buf);
        }

#pragma unroll
        for (int m = 0; m < 2; m++) {
            const int j = j0 + 8 * m;
            const int col = (dir == 1) ? j : (128 + j);
#pragma unroll
            for (int bs = 0; bs < 2; bs++) {
                const int q = 2 * m + bs;
                const int bg = b0 + (bs ? bq1 : bq0);
                out[((size_t)bg * NLAB + l) * 256 + col] = h[q];
            }
        }
    } else {
        // =========== PRODUCER: gi GEMM (R14 single-pass structure) ===========
        const int pw = wid - 8;            // 0..3
        const int ptid = tid - 256;        // 0..127
        const __half* Wp = g_wh + (size_t)p * G3 * DIM;
        const uint32_t Asm = smem_u + OFF_A;
        const uint32_t Bsm = smem_u + OFF_B;
        const int lrow = lane & 15;
        const int lhi  = lane >> 4;
        const int rB_lo = ((lane >> 4) << 3) + (lane & 7);
        const int cB = (lane >> 3) & 1;

        for (int j = 0; j < nseg; j++) {
            const int buf = j & 1;
            if (j >= 2) mbar_wait(mb_empty0 + 8 * buf, ((j - 2) >> 1) & 1);
            asm volatile("bar.sync 2, 128;" ::: "memory");   // old A fully consumed

            // issue A tile (M=64 rows = tt*8+b, K=256)
            const int tbase = dir ? (maxlen - 1 - TS * j) : TS * j;
#pragma unroll
            for (int i = 0; i < 16; i++) {
                int flat = ptid + 128 * i;             // 0..2047
                int kc = flat >> 9, rem = flat & 511;
                int row = rem >> 3, c = rem & 7;
                int b = row & 7, tt = row >> 3;
                int t = dir ? (tbase - tt) : (tbase + tt);
                t = min(max(t, 0), SEQ - 1);
                const __half* src = g_xh + ((size_t)(b0 + b) * SEQ + t) * DIM + kc * 64 + c * 8;
                uint32_t dst = Asm + (uint32_t)(kc * 8192 + row * 128 + ((c ^ (row & 7)) * 16));
                asm volatile("cp.async.cg.shared.global [%0], [%1], 16;\n"
                             :: "r"(dst), "l"(src) : "memory");
            }
            asm volatile("cp.async.commit_group;\n" ::: "memory");
            // issue B chunks 0,1 (each: 384 rows x 32 k)
#pragma unroll
            for (int kc32 = 0; kc32 < 2; kc32++) {
#pragma unroll
                for (int i = 0; i < 12; i++) {
                    int flat = ptid + 128 * i;         // 0..1535
                    int row = flat >> 2, c = flat & 3;
                    const __half* src = Wp + (size_t)row * DIM + kc32 * 32 + c * 8;
                    uint32_t dst = Bsm + (uint32_t)(kc32 * 24576 + row * 64 + ((c ^ (row & 3)) * 16));
                    asm volatile("cp.async.cg.shared.global [%0], [%1], 16;\n"
                                 :: "r"(dst), "l"(src) : "memory");
                }
                asm volatile("cp.async.commit_group;\n" ::: "memory");
            }

            // accumulators: rz in f16 (8 ntiles), n in f32 (4 ntiles), 4 mtiles
            uint32_t accH[4][8][2];
            float accF[4][4][4];
#pragma unroll
            for (int mt = 0; mt < 4; mt++) {
#pragma unroll
                for (int e = 0; e < 8; e++) { accH[mt][e][0] = 0u; accH[mt][e][1] = 0u; }
#pragma unroll
                for (int f = 0; f < 4; f++)
#pragma unroll
                    for (int q = 0; q < 4; q++) accF[mt][f][q] = 0.0f;
            }

            for (int kc32 = 0; kc32 < 8; kc32++) {
                asm volatile("cp.async.wait_group 1;\n" ::: "memory");
                asm volatile("bar.sync 2, 128;" ::: "memory");   // chunk kc32 visible
                const uint32_t Bb = Bsm + (uint32_t)((kc32 & 1) * 24576);
#pragma unroll
                for (int ksb = 0; ksb < 2; ksb++) {
                    const int ks = kc32 * 2 + ksb;
                    const uint32_t Abk = Asm + (uint32_t)((ks >> 2) * 8192);
                    const int ach = ((ks & 3) * 2 + lhi);
                    uint32_t bfrz[4][4], bfn[2][4];
#pragma unroll
                    for (int pr = 0; pr < 4; pr++) {
                        int nb = (pr < 2 ? 0 : 128) + 32 * pw + (pr & 1) * 16;
                        uint32_t addr = Bb + (uint32_t)((nb + rB_lo) * 64 +
                                        (((ksb * 2 + cB) ^ ((nb + rB_lo) & 3)) * 16));
                        ldm_x4(bfrz[pr][0], bfrz[pr][1], bfrz[pr][2], bfrz[pr][3], addr);
                    }
#pragma unroll
                    for (int pr = 0; pr < 2; pr++) {
                        int nb = 256 + 32 * pw + pr * 16;
                        uint32_t addr = Bb + (uint32_t)((nb + rB_lo) * 64 +
                                        (((ksb * 2 + cB) ^ ((nb + rB_lo) & 3)) * 16));
                        ldm_x4(bfn[pr][0], bfn[pr][1], bfn[pr][2], bfn[pr][3], addr);
                    }
#pragma unroll
                    for (int mt = 0; mt < 4; mt++) {
                        int rA = mt * 16 + lrow;
                        uint32_t af[4];
                        uint32_t addr = Abk + (uint32_t)(rA * 128 + ((ach ^ (rA & 7)) * 16));
                        ldm_x4(af[0], af[1], af[2], af[3], addr);
#pragma unroll
                        for (int pr = 0; pr < 4; pr++) {
                            mma_f16h(accH[mt][2 * pr],     af, &bfrz[pr][0]);
                            mma_f16h(accH[mt][2 * pr + 1], af, &bfrz[pr][2]);
                        }
                        mma_f16(accF[mt][0], af, &bfn[0][0]);
                        mma_f16(accF[mt][1], af, &bfn[0][2]);
                        mma_f16(accF[mt][2], af, &bfn[1][0]);
                        mma_f16(accF[mt][3], af, &bfn[1][2]);
                    }
                }
                asm volatile("bar.sync 2, 128;" ::: "memory");   // chunk reads done
                if (kc32 + 2 < 8) {
                    const int nk = kc32 + 2;
#pragma unroll
                    for (int i = 0; i < 12; i++) {
                        int flat = ptid + 128 * i;
                        int row = flat >> 2, c = flat & 3;
                        const __half* src = Wp + (size_t)row * DIM + nk * 32 + c * 8;
                        uint32_t dst = Bsm + (uint32_t)((nk & 1) * 24576 + row * 64 +
                                                        ((c ^ (row & 3)) * 16));
                        asm volatile("cp.async.cg.shared.global [%0], [%1], 16;\n"
                                     :: "r"(dst), "l"(src) : "memory");
                    }
                }
                asm volatile("cp.async.commit_group;\n" ::: "memory");
            }

            // epilogue: store raw gi (biases applied in recurrence)
            __half* gib = gi_sm + (size_t)buf * 64 * GIP;
#pragma unroll
            for (int mt = 0; mt < 4; mt++) {
                int rr0 = mt * 16 + gid, rr1 = rr0 + 8;
#pragma unroll
                for (int e = 0; e < 8; e++) {
                    int col = ((e < 4) ? (32 * pw + 8 * e) : (128 + 32 * pw + 8 * (e - 4)))
                              + 2 * tig;
                    *(uint32_t*)(gib + (size_t)rr0 * GIP + col) = accH[mt][e][0];
                    *(uint32_t*)(gib + (size_t)rr1 * GIP + col) = accH[mt][e][1];
                }
#pragma unroll
                for (int f = 0; f < 4; f++) {
                    int col = 256 + 32 * pw + 8 * f + 2 * tig;
                    *(uint32_t*)(gib + (size_t)rr0 * GIP + col) =
                        f2h2(accF[mt][f][0], accF[mt][f][1]);
                    *(uint32_t*)(gib + (size_t)rr1 * GIP + col) =
                        f2h2(accF[mt][f][2], accF[mt][f][3]);
                }
            }
            mbar_arrive(mb_full0 + 8 * buf);
        }
    }
}

extern "C" void kernel_launch(void* const* d_in, const int* in_sizes, int n_in,
                              void* d_out, int out_size) {
    const float* x     = (const float*)d_in[0];
    const int*   amask = (const int*)d_in[1];
    // d_in[2] = label: always arange(L) by construction.
    const float* Wih   = (const float*)d_in[3];
    const float* Whh   = (const float*)d_in[4];
    const float* bih   = (const float*)d_in[5];
    const float* bhh   = (const float*)d_in[6];
    float*       out   = (float*)d_out;

    cudaFuncSetAttribute(gru_fused_kernel, cudaFuncAttributeMaxDynamicSharedMemorySize,
                         SMEM_TOTAL);

    const size_t nchunks = (size_t)BATCH * SEQ * DIM / 4 + (size_t)NPAIR * G3 * DIM / 4;
    convert_kernel<<<(unsigned)((nchunks + 255) / 256), 256>>>(x, Wih);

    dim3 g(4, 32);
    gru_fused_kernel<<<g, 384, SMEM_TOTAL>>>(Whh, bih, bhh, amask, out);
}